// round 7
// baseline (speedup 1.0000x reference)
#include <cuda_runtime.h>
#include <cstdint>

#define SQ_ 0.09016844005556022f   // (1/16)*log2(e)

static __device__ float g_Q [18874368];   // [g][s][d]  scaled by SQ_, tf32-rounded
static __device__ float g_K [18874368];   // [g][s][d]  tf32-rounded
static __device__ float g_Vt[18874368];   // [g][e][s]  tf32-rounded

__device__ __forceinline__ uint32_t smem_u32(const void* p) {
    uint32_t a;
    asm("{ .reg .u64 t; cvta.to.shared.u64 t, %1; cvt.u32.u64 %0, t; }" : "=r"(a) : "l"(p));
    return a;
}
__device__ __forceinline__ void cpa16(uint32_t d, const void* s) {
    asm volatile("cp.async.cg.shared.global [%0], [%1], 16;\n" :: "r"(d), "l"(s));
}
#define CP_COMMIT  asm volatile("cp.async.commit_group;\n" ::: "memory")
#define CP_WAIT(n) asm volatile("cp.async.wait_group %0;\n" :: "n"(n) : "memory")

__device__ __forceinline__ uint32_t f2tf(float x) {
    uint32_t u; asm("cvt.rna.tf32.f32 %0, %1;" : "=r"(u) : "f"(x)); return u;
}
__device__ __forceinline__ void mma8(float* c, const uint32_t* a, const uint32_t* b) {
    asm volatile("mma.sync.aligned.m16n8k8.row.col.f32.tf32.tf32.f32 "
                 "{%0,%1,%2,%3}, {%4,%5,%6,%7}, {%8,%9}, {%0,%1,%2,%3};\n"
                 : "+f"(c[0]), "+f"(c[1]), "+f"(c[2]), "+f"(c[3])
                 : "r"(a[0]), "r"(a[1]), "r"(a[2]), "r"(a[3]), "r"(b[0]), "r"(b[1]));
}

// ============================================================
// QKV: D[s,e] = X[s,:]·W[e,:]^T + b.  CTA 128x128, K-chunks 32, 256 thr.
// Single sync per chunk: wait -> sync -> stage(next) -> compute.
// Outputs tf32-rounded so attention needs no cvt.
// ============================================================
#define QKV_SMEM 73728

__global__ void __launch_bounds__(256, 2)
qkv_mma(const float* __restrict__ x,
        const float* __restrict__ Wq, const float* __restrict__ bq,
        const float* __restrict__ Wk, const float* __restrict__ bk,
        const float* __restrict__ Wv, const float* __restrict__ bv)
{
    extern __shared__ float smf[];
    float* As = smf;            // 2 x 4608
    float* Bs = smf + 9216;     // 2 x 4608

    const int tile = blockIdx.x, g = blockIdx.y, z = blockIdx.z;
    const int tm = tile >> 1, tn = tile & 1;
    const int hh = g % 3;
    const int tid = threadIdx.x, wid = tid >> 5, lane = tid & 31;
    const int ty = lane >> 2, tx = lane & 3;
    const int warpM = wid >> 1, warpN = wid & 1;
    const int rb = warpM * 32, nb = warpN * 64;

    const float* W; const float* bias;
    if (z == 0)      { W = Wq; bias = bq; }
    else if (z == 1) { W = Wk; bias = bk; }
    else             { W = Wv; bias = bv; }
    W += hh * 65536;  bias += hh * 256;

    const float* X  = x + ((size_t)((g / 3) * 1024 + tm * 128)) * 768 + hh * 256;
    const float* Wp = W + tn * 128 * 256;
    const uint32_t sA = smem_u32(As), sB = smem_u32(Bs);

    auto stage = [&](int dc_, int bf_) {
        uint32_t dA = sA + bf_ * 18432, dB = sB + bf_ * 18432;
#pragma unroll
        for (int it = 0; it < 4; it++) {
            int i = tid + it * 256, r = i >> 3, c4 = i & 7;
            cpa16(dA + r * 144 + c4 * 16, X  + (size_t)r * 768 + dc_ * 32 + c4 * 4);
            cpa16(dB + r * 144 + c4 * 16, Wp + r * 256 + dc_ * 32 + c4 * 4);
        }
        CP_COMMIT;
    };

    float acc[2][8][4];
#pragma unroll
    for (int mf = 0; mf < 2; mf++)
#pragma unroll
        for (int nf = 0; nf < 8; nf++)
#pragma unroll
            for (int k = 0; k < 4; k++) acc[mf][nf][k] = 0.f;

    stage(0, 0);
#pragma unroll 1
    for (int dc = 0; dc < 8; dc++) {
        const int bf = dc & 1;
        CP_WAIT(0);
        __syncthreads();
        if (dc < 7) stage(dc + 1, bf ^ 1);
        const float* Aq = As + bf * 4608;
        const float* Bk = Bs + bf * 4608;
#pragma unroll
        for (int ks = 0; ks < 4; ks++) {
            uint32_t af[2][4], bfr[8][2];
            const int kc = ks * 8 + tx;
#pragma unroll
            for (int mf = 0; mf < 2; mf++) {
                const float* ap = Aq + (rb + mf * 16 + ty) * 36 + kc;
                af[mf][0] = f2tf(ap[0]);
                af[mf][1] = f2tf(ap[8 * 36]);
                af[mf][2] = f2tf(ap[4]);
                af[mf][3] = f2tf(ap[8 * 36 + 4]);
            }
#pragma unroll
            for (int nf = 0; nf < 8; nf++) {
                const float* bp = Bk + (nb + nf * 8 + ty) * 36 + kc;
                bfr[nf][0] = f2tf(bp[0]);
                bfr[nf][1] = f2tf(bp[4]);
            }
#pragma unroll
            for (int mf = 0; mf < 2; mf++)
#pragma unroll
                for (int nf = 0; nf < 8; nf++)
                    mma8(acc[mf][nf], af[mf], bfr[nf]);
        }
    }

    if (z < 2) {
        float* dst = (z == 0 ? g_Q : g_K) + (size_t)g * 262144;
        const float osc = (z == 0) ? SQ_ : 1.0f;
#pragma unroll
        for (int mf = 0; mf < 2; mf++) {
            const int r0 = tm * 128 + rb + mf * 16 + ty, r1 = r0 + 8;
#pragma unroll
            for (int nf = 0; nf < 8; nf++) {
                const int ccol = tn * 128 + nb + nf * 8 + tx * 2;
                const float b0 = __ldg(&bias[ccol]), b1 = __ldg(&bias[ccol + 1]);
                *(float2*)&dst[(size_t)r0 * 256 + ccol] = make_float2(
                    __uint_as_float(f2tf((acc[mf][nf][0] + b0) * osc)),
                    __uint_as_float(f2tf((acc[mf][nf][1] + b1) * osc)));
                *(float2*)&dst[(size_t)r1 * 256 + ccol] = make_float2(
                    __uint_as_float(f2tf((acc[mf][nf][2] + b0) * osc)),
                    __uint_as_float(f2tf((acc[mf][nf][3] + b1) * osc)));
            }
        }
    } else {
        float* dst = g_Vt + (size_t)g * 262144;
#pragma unroll
        for (int mf = 0; mf < 2; mf++) {
            const int r0 = tm * 128 + rb + mf * 16 + ty, r1 = r0 + 8;
#pragma unroll
            for (int nf = 0; nf < 8; nf++) {
                const int e0 = tn * 128 + nb + nf * 8 + tx * 2;
                const float b0 = __ldg(&bias[e0]), b1 = __ldg(&bias[e0 + 1]);
                dst[(size_t)e0 * 1024 + r0]       = __uint_as_float(f2tf(acc[mf][nf][0] + b0));
                dst[(size_t)(e0 + 1) * 1024 + r0] = __uint_as_float(f2tf(acc[mf][nf][1] + b1));
                dst[(size_t)e0 * 1024 + r1]       = __uint_as_float(f2tf(acc[mf][nf][2] + b0));
                dst[(size_t)(e0 + 1) * 1024 + r1] = __uint_as_float(f2tf(acc[mf][nf][3] + b1));
            }
        }
    }
}

// ============================================================
// Attention: per (qtile=128, g).  512 thr, 16 warps (4M x 4N).
// S warp-tile 32x32; PV warp-tile 32x64. Inputs pre-rounded tf32 -> no cvt.
// Single sync per chunk. smem: A 2x4608 | B 2x5120 | P 128x132 | lp 512
// ============================================================
#define ATT_SMEM 147456

__global__ void __launch_bounds__(512, 1)
attn_mma(float* __restrict__ out)
{
    extern __shared__ float smf[];
    float* As = smf;                 // Q chunks 2 x 4608
    float* Bs = smf + 9216;          // K / Vt chunks 2 x 5120
    float* Ps = smf + 19456;         // 128 x 132 (tf32-rounded)
    float* lp = smf + 36352;         // 512

    const int qt = blockIdx.x, g = blockIdx.y;
    const int bb = g / 9, cc = (g / 3) % 3, hh = g % 3;
    const int q0 = qt * 128;
    const int tid = threadIdx.x, wid = tid >> 5, lane = tid & 31;
    const int ty = lane >> 2, tx = lane & 3;
    const int warpM = wid & 3, warpN = wid >> 2;
    const int rb = warpM * 32, nbS = warpN * 32, nbO = warpN * 64;
    const size_t gbase = (size_t)g * 262144;
    const float* Qg = g_Q + gbase + (size_t)q0 * 256;
    const float* Kg = g_K + gbase;
    const float* Vg = g_Vt + gbase;
    const uint32_t sA = smem_u32(As), sB = smem_u32(Bs);
    const uint32_t* Pu = (const uint32_t*)Ps;

    auto stageQK = [&](int t_, int dc_, int bf_) {
        const float* Qc = Qg + dc_ * 32;
        const float* Kc = Kg + (size_t)t_ * 32768 + dc_ * 32;
        uint32_t dA = sA + bf_ * 18432, dB = sB + bf_ * 20480;
#pragma unroll
        for (int it = 0; it < 2; it++) {
            int i = tid + it * 512, r = i >> 3, c4 = i & 7;
            cpa16(dA + r * 144 + c4 * 16, Qc + (size_t)r * 256 + c4 * 4);
            cpa16(dB + r * 144 + c4 * 16, Kc + (size_t)r * 256 + c4 * 4);
        }
        CP_COMMIT;
    };
    auto stageV = [&](int t_, int jc_, int bf_) {
        const float* Vc = Vg + t_ * 128 + jc_ * 16;
        uint32_t dB = sB + bf_ * 20480;
#pragma unroll
        for (int it = 0; it < 2; it++) {
            int i = tid + it * 512, e = i >> 2, c4 = i & 3;
            cpa16(dB + e * 80 + c4 * 16, Vc + (size_t)e * 1024 + c4 * 4);
        }
        CP_COMMIT;
    };

    float Oac[2][8][4];
    float lac[4] = {0.f, 0.f, 0.f, 0.f};
#pragma unroll
    for (int mf = 0; mf < 2; mf++)
#pragma unroll
        for (int nf = 0; nf < 8; nf++)
#pragma unroll
            for (int k = 0; k < 4; k++) Oac[mf][nf][k] = 0.f;

    stageQK(0, 0, 0);

#pragma unroll 1
    for (int t = 0; t < 8; t++) {
        float Sac[2][4][4];
#pragma unroll
        for (int mf = 0; mf < 2; mf++)
#pragma unroll
            for (int nf = 0; nf < 4; nf++)
#pragma unroll
                for (int k = 0; k < 4; k++) Sac[mf][nf][k] = 0.f;

        // ---- S = Q·K^T ----
#pragma unroll 1
        for (int dc = 0; dc < 8; dc++) {
            const int bf = dc & 1;
            CP_WAIT(0);
            __syncthreads();
            if (dc < 7) stageQK(t, dc + 1, bf ^ 1);
            else        stageV(t, 0, bf ^ 1);
            const uint32_t* Aq = (const uint32_t*)(As + bf * 4608);
            const uint32_t* Bk = (const uint32_t*)(Bs + bf * 5120);
#pragma unroll
            for (int ks = 0; ks < 4; ks++) {
                uint32_t af[2][4], bfr[4][2];
                const int kc = ks * 8 + tx;
#pragma unroll
                for (int mf = 0; mf < 2; mf++) {
                    const uint32_t* ap = Aq + (rb + mf * 16 + ty) * 36 + kc;
                    af[mf][0] = ap[0];
                    af[mf][1] = ap[8 * 36];
                    af[mf][2] = ap[4];
                    af[mf][3] = ap[8 * 36 + 4];
                }
#pragma unroll
                for (int nf = 0; nf < 4; nf++) {
                    const uint32_t* bp = Bk + (nbS + nf * 8 + ty) * 36 + kc;
                    bfr[nf][0] = bp[0];
                    bfr[nf][1] = bp[4];
                }
#pragma unroll
                for (int mf = 0; mf < 2; mf++)
#pragma unroll
                    for (int nf = 0; nf < 4; nf++)
                        mma8(Sac[mf][nf], af[mf], bfr[nf]);
            }
        }

        // ---- softmax: P = exp2(S), running row-sums; P tf32-rounded ----
#pragma unroll
        for (int mf = 0; mf < 2; mf++) {
            const int r = rb + mf * 16 + ty;
#pragma unroll
            for (int nf = 0; nf < 4; nf++) {
                float e0 = exp2f(Sac[mf][nf][0]);
                float e1 = exp2f(Sac[mf][nf][1]);
                float e2 = exp2f(Sac[mf][nf][2]);
                float e3 = exp2f(Sac[mf][nf][3]);
                lac[mf * 2]     += e0 + e1;
                lac[mf * 2 + 1] += e2 + e3;
                const int ccol = nbS + nf * 8 + tx * 2;
                *(float2*)&Ps[r * 132 + ccol] = make_float2(
                    __uint_as_float(f2tf(e0)), __uint_as_float(f2tf(e1)));
                *(float2*)&Ps[(r + 8) * 132 + ccol] = make_float2(
                    __uint_as_float(f2tf(e2)), __uint_as_float(f2tf(e3)));
            }
        }
        __syncthreads();

        // ---- O += P·Vt ----
#pragma unroll 1
        for (int jc = 0; jc < 8; jc++) {
            const int bf = jc & 1;
            CP_WAIT(0);
            __syncthreads();
            if (jc < 7)      stageV(t, jc + 1, bf ^ 1);
            else if (t < 7)  stageQK(t + 1, 0, 0);
            const uint32_t* Vt_ = (const uint32_t*)(Bs + bf * 5120);
#pragma unroll
            for (int ks = 0; ks < 2; ks++) {
                uint32_t af[2][4], bfr[8][2];
                const int pc = jc * 16 + ks * 8 + tx;
#pragma unroll
                for (int mf = 0; mf < 2; mf++) {
                    const uint32_t* pp = Pu + (rb + mf * 16 + ty) * 132 + pc;
                    af[mf][0] = pp[0];
                    af[mf][1] = pp[8 * 132];
                    af[mf][2] = pp[4];
                    af[mf][3] = pp[8 * 132 + 4];
                }
#pragma unroll
                for (int nf = 0; nf < 8; nf++) {
                    const uint32_t* vp = Vt_ + (nbO + nf * 8 + ty) * 20 + ks * 8 + tx;
                    bfr[nf][0] = vp[0];
                    bfr[nf][1] = vp[4];
                }
#pragma unroll
                for (int mf = 0; mf < 2; mf++)
#pragma unroll
                    for (int nf = 0; nf < 8; nf++)
                        mma8(Oac[mf][nf], af[mf], bfr[nf]);
            }
        }
    }

    // ---- epilogue ----
#pragma unroll
    for (int i = 0; i < 4; i++) {
        lac[i] += __shfl_xor_sync(0xffffffffu, lac[i], 1);
        lac[i] += __shfl_xor_sync(0xffffffffu, lac[i], 2);
    }
    __syncthreads();
    if (tx == 0) {
#pragma unroll
        for (int mf = 0; mf < 2; mf++) {
            lp[warpN * 128 + rb + mf * 16 + ty]     = lac[mf * 2];
            lp[warpN * 128 + rb + mf * 16 + ty + 8] = lac[mf * 2 + 1];
        }
    }
    __syncthreads();
#pragma unroll
    for (int mf = 0; mf < 2; mf++) {
        const int r0 = rb + mf * 16 + ty, r1 = r0 + 8;
        const float inv0 = 1.f / (lp[r0] + lp[128 + r0] + lp[256 + r0] + lp[384 + r0]);
        const float inv1 = 1.f / (lp[r1] + lp[128 + r1] + lp[256 + r1] + lp[384 + r1]);
        float* o0 = out + ((size_t)(bb * 1024 + q0 + r0)) * 2304 + cc * 768 + hh * 256 + nbO;
        float* o1 = out + ((size_t)(bb * 1024 + q0 + r1)) * 2304 + cc * 768 + hh * 256 + nbO;
#pragma unroll
        for (int nf = 0; nf < 8; nf++) {
            const int ccol = nf * 8 + tx * 2;
            *(float2*)&o0[ccol] = make_float2(Oac[mf][nf][0] * inv0, Oac[mf][nf][1] * inv0);
            *(float2*)&o1[ccol] = make_float2(Oac[mf][nf][2] * inv1, Oac[mf][nf][3] * inv1);
        }
    }
}

// ============================================================
extern "C" void kernel_launch(void* const* d_in, const int* in_sizes, int n_in,
                              void* d_out, int out_size)
{
    const float* x  = (const float*)d_in[0];
    const float* Wq = (const float*)d_in[1];
    const float* bq = (const float*)d_in[2];
    const float* Wk = (const float*)d_in[3];
    const float* bk = (const float*)d_in[4];
    const float* Wv = (const float*)d_in[5];
    const float* bv = (const float*)d_in[6];
    float* out = (float*)d_out;

    cudaFuncSetAttribute(qkv_mma,  cudaFuncAttributeMaxDynamicSharedMemorySize, QKV_SMEM);
    cudaFuncSetAttribute(attn_mma, cudaFuncAttributeMaxDynamicSharedMemorySize, ATT_SMEM);

    qkv_mma<<<dim3(16, 72, 3), 256, QKV_SMEM>>>(x, Wq, bq, Wk, bk, Wv, bv);
    attn_mma<<<dim3(8, 72), 512, ATT_SMEM>>>(out);
}

// round 8
// speedup vs baseline: 1.0895x; 1.0895x over previous
#include <cuda_runtime.h>
#include <cstdint>

#define SQ_ 0.09016844005556022f   // (1/16)*log2(e)

static __device__ float g_Q [18874368];   // [g][s][d]  scaled by SQ_, tf32-rounded
static __device__ float g_K [18874368];   // [g][s][d]  tf32-rounded
static __device__ float g_Vt[18874368];   // [g][e][s]  tf32-rounded

__device__ __forceinline__ uint32_t smem_u32(const void* p) {
    uint32_t a;
    asm("{ .reg .u64 t; cvta.to.shared.u64 t, %1; cvt.u32.u64 %0, t; }" : "=r"(a) : "l"(p));
    return a;
}
__device__ __forceinline__ void cpa16(uint32_t d, const void* s) {
    asm volatile("cp.async.cg.shared.global [%0], [%1], 16;\n" :: "r"(d), "l"(s));
}
#define CP_COMMIT  asm volatile("cp.async.commit_group;\n" ::: "memory")
#define CP_WAIT(n) asm volatile("cp.async.wait_group %0;\n" :: "n"(n) : "memory")

__device__ __forceinline__ uint32_t f2tf(float x) {
    uint32_t u; asm("cvt.rna.tf32.f32 %0, %1;" : "=r"(u) : "f"(x)); return u;
}
__device__ __forceinline__ void mma8(float* c, const uint32_t* a, const uint32_t* b) {
    asm volatile("mma.sync.aligned.m16n8k8.row.col.f32.tf32.tf32.f32 "
                 "{%0,%1,%2,%3}, {%4,%5,%6,%7}, {%8,%9}, {%0,%1,%2,%3};\n"
                 : "+f"(c[0]), "+f"(c[1]), "+f"(c[2]), "+f"(c[3])
                 : "r"(a[0]), "r"(a[1]), "r"(a[2]), "r"(a[3]), "r"(b[0]), "r"(b[1]));
}

// ============================================================
// QKV: D[s,e] = X[s,:]·W[e,:]^T + b.  CTA 128x128, K-chunks 32, 256 thr.
// 3-stage cp.async ring: wait(1) -> sync -> stage(dc+2) -> compute(dc).
// Outputs tf32-rounded (Q also pre-scaled by SQ_); V transposed.
// smem: A 3x4608f, B 3x4608f = 110592 B  -> 2 CTAs/SM
// ============================================================
#define QKV_SMEM 110592

__global__ void __launch_bounds__(256, 2)
qkv_mma(const float* __restrict__ x,
        const float* __restrict__ Wq, const float* __restrict__ bq,
        const float* __restrict__ Wk, const float* __restrict__ bk,
        const float* __restrict__ Wv, const float* __restrict__ bv)
{
    extern __shared__ float smf[];
    float* As = smf;            // 3 x 4608
    float* Bs = smf + 13824;    // 3 x 4608

    const int tile = blockIdx.x, g = blockIdx.y, z = blockIdx.z;
    const int tm = tile >> 1, tn = tile & 1;
    const int hh = g % 3;
    const int tid = threadIdx.x, wid = tid >> 5, lane = tid & 31;
    const int ty = lane >> 2, tx = lane & 3;
    const int warpM = wid >> 1, warpN = wid & 1;
    const int rb = warpM * 32, nb = warpN * 64;

    const float* W; const float* bias;
    if (z == 0)      { W = Wq; bias = bq; }
    else if (z == 1) { W = Wk; bias = bk; }
    else             { W = Wv; bias = bv; }
    W += hh * 65536;  bias += hh * 256;

    const float* X  = x + ((size_t)((g / 3) * 1024 + tm * 128)) * 768 + hh * 256;
    const float* Wp = W + tn * 128 * 256;
    const uint32_t sA = smem_u32(As), sB = smem_u32(Bs);

    auto stage = [&](int dc_) {
        if (dc_ >= 8) return;
        const int bf_ = dc_ % 3;
        uint32_t dA = sA + bf_ * 18432, dB = sB + bf_ * 18432;
#pragma unroll
        for (int it = 0; it < 4; it++) {
            int i = tid + it * 256, r = i >> 3, c4 = i & 7;
            cpa16(dA + r * 144 + c4 * 16, X  + (size_t)r * 768 + dc_ * 32 + c4 * 4);
            cpa16(dB + r * 144 + c4 * 16, Wp + r * 256 + dc_ * 32 + c4 * 4);
        }
        CP_COMMIT;
    };

    float acc[2][8][4];
#pragma unroll
    for (int mf = 0; mf < 2; mf++)
#pragma unroll
        for (int nf = 0; nf < 8; nf++)
#pragma unroll
            for (int k = 0; k < 4; k++) acc[mf][nf][k] = 0.f;

    stage(0); stage(1);
#pragma unroll 1
    for (int dc = 0; dc < 8; dc++) {
        const int bf = dc % 3;
        CP_WAIT(1);
        __syncthreads();
        stage(dc + 2);
        const float* Aq = As + bf * 4608;
        const float* Bk = Bs + bf * 4608;
#pragma unroll
        for (int ks = 0; ks < 4; ks++) {
            uint32_t af[2][4], bfr[8][2];
            const int kc = ks * 8 + tx;
#pragma unroll
            for (int mf = 0; mf < 2; mf++) {
                const float* ap = Aq + (rb + mf * 16 + ty) * 36 + kc;
                af[mf][0] = f2tf(ap[0]);
                af[mf][1] = f2tf(ap[8 * 36]);
                af[mf][2] = f2tf(ap[4]);
                af[mf][3] = f2tf(ap[8 * 36 + 4]);
            }
#pragma unroll
            for (int nf = 0; nf < 8; nf++) {
                const float* bp = Bk + (nb + nf * 8 + ty) * 36 + kc;
                bfr[nf][0] = f2tf(bp[0]);
                bfr[nf][1] = f2tf(bp[4]);
            }
#pragma unroll
            for (int mf = 0; mf < 2; mf++)
#pragma unroll
                for (int nf = 0; nf < 8; nf++)
                    mma8(acc[mf][nf], af[mf], bfr[nf]);
        }
    }

    if (z < 2) {
        float* dst = (z == 0 ? g_Q : g_K) + (size_t)g * 262144;
        const float osc = (z == 0) ? SQ_ : 1.0f;
#pragma unroll
        for (int mf = 0; mf < 2; mf++) {
            const int r0 = tm * 128 + rb + mf * 16 + ty, r1 = r0 + 8;
#pragma unroll
            for (int nf = 0; nf < 8; nf++) {
                const int ccol = tn * 128 + nb + nf * 8 + tx * 2;
                const float b0 = __ldg(&bias[ccol]), b1 = __ldg(&bias[ccol + 1]);
                *(float2*)&dst[(size_t)r0 * 256 + ccol] = make_float2(
                    __uint_as_float(f2tf((acc[mf][nf][0] + b0) * osc)),
                    __uint_as_float(f2tf((acc[mf][nf][1] + b1) * osc)));
                *(float2*)&dst[(size_t)r1 * 256 + ccol] = make_float2(
                    __uint_as_float(f2tf((acc[mf][nf][2] + b0) * osc)),
                    __uint_as_float(f2tf((acc[mf][nf][3] + b1) * osc)));
            }
        }
    } else {
        float* dst = g_Vt + (size_t)g * 262144;
#pragma unroll
        for (int mf = 0; mf < 2; mf++) {
            const int r0 = tm * 128 + rb + mf * 16 + ty, r1 = r0 + 8;
#pragma unroll
            for (int nf = 0; nf < 8; nf++) {
                const int e0 = tn * 128 + nb + nf * 8 + tx * 2;
                const float b0 = __ldg(&bias[e0]), b1 = __ldg(&bias[e0 + 1]);
                dst[(size_t)e0 * 1024 + r0]       = __uint_as_float(f2tf(acc[mf][nf][0] + b0));
                dst[(size_t)(e0 + 1) * 1024 + r0] = __uint_as_float(f2tf(acc[mf][nf][1] + b1));
                dst[(size_t)e0 * 1024 + r1]       = __uint_as_float(f2tf(acc[mf][nf][2] + b0));
                dst[(size_t)(e0 + 1) * 1024 + r1] = __uint_as_float(f2tf(acc[mf][nf][3] + b1));
            }
        }
    }
}

// ============================================================
// Attention: per (qtile=128, g).  256 thr, 8 warps (4M x 2N).
// S warp-tile 32x64; PV warp-tile 32x128. 3-stage global cp.async ring over
// 128 chunks (per t: 8 QK then 8 Vt).  Inputs pre-rounded tf32.
// smem: A 3x4608 | B 3x5120 | P 128x132 | lp 256  = 185344 B
// ============================================================
#define ATT_SMEM 185344

__global__ void __launch_bounds__(256, 1)
attn_mma(float* __restrict__ out)
{
    extern __shared__ float smf[];
    float* As = smf;                 // 3 x 4608
    float* Bs = smf + 13824;         // 3 x 5120
    float* Ps = smf + 29184;         // 128 x 132 (tf32-rounded)
    float* lp = smf + 46080;         // 256

    const int qt = blockIdx.x, g = blockIdx.y;
    const int bb = g / 9, cc = (g / 3) % 3, hh = g % 3;
    const int q0 = qt * 128;
    const int tid = threadIdx.x, wid = tid >> 5, lane = tid & 31;
    const int ty = lane >> 2, tx = lane & 3;
    const int warpM = wid >> 1, warpN = wid & 1;
    const int rb = warpM * 32, nbS = warpN * 64, nbO = warpN * 128;
    const size_t gbase = (size_t)g * 262144;
    const float* Qg = g_Q + gbase + (size_t)q0 * 256;
    const float* Kg = g_K + gbase;
    const float* Vg = g_Vt + gbase;
    const uint32_t sA = smem_u32(As), sB = smem_u32(Bs);
    const uint32_t* Pu = (const uint32_t*)Ps;

    // global chunk schedule: idx in [0,128); per t: c=idx&15, c<8 -> QK chunk c,
    // else Vt chunk c-8.  Buffer = idx % 3.
    auto stage = [&](int idx) {
        if (idx >= 128) return;
        const int t_ = idx >> 4, c_ = idx & 15, bf_ = idx % 3;
        if (c_ < 8) {
            const float* Qc = Qg + c_ * 32;
            const float* Kc = Kg + (size_t)t_ * 32768 + c_ * 32;
            uint32_t dA = sA + bf_ * 18432, dB = sB + bf_ * 20480;
#pragma unroll
            for (int it = 0; it < 4; it++) {
                int i = tid + it * 256, r = i >> 3, c4 = i & 7;
                cpa16(dA + r * 144 + c4 * 16, Qc + (size_t)r * 256 + c4 * 4);
                cpa16(dB + r * 144 + c4 * 16, Kc + (size_t)r * 256 + c4 * 4);
            }
        } else {
            const float* Vc = Vg + t_ * 128 + (c_ - 8) * 16;
            uint32_t dB = sB + bf_ * 20480;
#pragma unroll
            for (int it = 0; it < 4; it++) {
                int i = tid + it * 256, e = i >> 2, c4 = i & 3;
                cpa16(dB + e * 80 + c4 * 16, Vc + (size_t)e * 1024 + c4 * 4);
            }
        }
        CP_COMMIT;
    };

    float Oac[2][16][4];
    float Sac[2][8][4];
    float lac[4] = {0.f, 0.f, 0.f, 0.f};
#pragma unroll
    for (int mf = 0; mf < 2; mf++)
#pragma unroll
        for (int nf = 0; nf < 16; nf++)
#pragma unroll
            for (int k = 0; k < 4; k++) Oac[mf][nf][k] = 0.f;

    stage(0); stage(1);

#pragma unroll 1
    for (int t = 0; t < 8; t++) {
#pragma unroll
        for (int mf = 0; mf < 2; mf++)
#pragma unroll
            for (int nf = 0; nf < 8; nf++)
#pragma unroll
                for (int k = 0; k < 4; k++) Sac[mf][nf][k] = 0.f;

        // ---- S = Q·K^T : 8 QK chunks ----
#pragma unroll 1
        for (int dc = 0; dc < 8; dc++) {
            const int idx = t * 16 + dc;
            const int bf = idx % 3;
            CP_WAIT(1);
            __syncthreads();
            stage(idx + 2);
            const uint32_t* Aq = (const uint32_t*)(As + bf * 4608);
            const uint32_t* Bk = (const uint32_t*)(Bs + bf * 5120);
#pragma unroll
            for (int ks = 0; ks < 4; ks++) {
                uint32_t af[2][4], bfr[8][2];
                const int kc = ks * 8 + tx;
#pragma unroll
                for (int mf = 0; mf < 2; mf++) {
                    const uint32_t* ap = Aq + (rb + mf * 16 + ty) * 36 + kc;
                    af[mf][0] = ap[0];
                    af[mf][1] = ap[8 * 36];
                    af[mf][2] = ap[4];
                    af[mf][3] = ap[8 * 36 + 4];
                }
#pragma unroll
                for (int nf = 0; nf < 8; nf++) {
                    const uint32_t* bp = Bk + (nbS + nf * 8 + ty) * 36 + kc;
                    bfr[nf][0] = bp[0];
                    bfr[nf][1] = bp[4];
                }
#pragma unroll
                for (int mf = 0; mf < 2; mf++)
#pragma unroll
                    for (int nf = 0; nf < 8; nf++)
                        mma8(Sac[mf][nf], af[mf], bfr[nf]);
            }
        }

        // ---- softmax: P = exp2(S) (ref max 0), running row sums ----
#pragma unroll
        for (int mf = 0; mf < 2; mf++) {
            const int r = rb + mf * 16 + ty;
#pragma unroll
            for (int nf = 0; nf < 8; nf++) {
                float e0 = exp2f(Sac[mf][nf][0]);
                float e1 = exp2f(Sac[mf][nf][1]);
                float e2 = exp2f(Sac[mf][nf][2]);
                float e3 = exp2f(Sac[mf][nf][3]);
                lac[mf * 2]     += e0 + e1;
                lac[mf * 2 + 1] += e2 + e3;
                const int ccol = nbS + nf * 8 + tx * 2;
                *(float2*)&Ps[r * 132 + ccol] = make_float2(
                    __uint_as_float(f2tf(e0)), __uint_as_float(f2tf(e1)));
                *(float2*)&Ps[(r + 8) * 132 + ccol] = make_float2(
                    __uint_as_float(f2tf(e2)), __uint_as_float(f2tf(e3)));
            }
        }
        // P-write / P-read ordering handled by the sync at the next chunk.

        // ---- O += P·Vt : 8 Vt chunks ----
#pragma unroll 1
        for (int jc = 0; jc < 8; jc++) {
            const int idx = t * 16 + 8 + jc;
            const int bf = idx % 3;
            CP_WAIT(1);
            __syncthreads();
            stage(idx + 2);
            const uint32_t* Vt_ = (const uint32_t*)(Bs + bf * 5120);
#pragma unroll
            for (int ks = 0; ks < 2; ks++) {
                uint32_t af[2][4], bfr[16][2];
                const int pc = jc * 16 + ks * 8 + tx;
#pragma unroll
                for (int mf = 0; mf < 2; mf++) {
                    const uint32_t* pp = Pu + (rb + mf * 16 + ty) * 132 + pc;
                    af[mf][0] = pp[0];
                    af[mf][1] = pp[8 * 132];
                    af[mf][2] = pp[4];
                    af[mf][3] = pp[8 * 132 + 4];
                }
#pragma unroll
                for (int nf = 0; nf < 16; nf++) {
                    const uint32_t* vp = Vt_ + (nbO + nf * 8 + ty) * 20 + ks * 8 + tx;
                    bfr[nf][0] = vp[0];
                    bfr[nf][1] = vp[4];
                }
#pragma unroll
                for (int mf = 0; mf < 2; mf++)
#pragma unroll
                    for (int nf = 0; nf < 16; nf++)
                        mma8(Oac[mf][nf], af[mf], bfr[nf]);
            }
        }
    }

    // ---- epilogue: reduce row sums, O/l, store ----
#pragma unroll
    for (int i = 0; i < 4; i++) {
        lac[i] += __shfl_xor_sync(0xffffffffu, lac[i], 1);
        lac[i] += __shfl_xor_sync(0xffffffffu, lac[i], 2);
    }
    __syncthreads();
    if (tx == 0) {
#pragma unroll
        for (int mf = 0; mf < 2; mf++) {
            lp[warpN * 128 + rb + mf * 16 + ty]     = lac[mf * 2];
            lp[warpN * 128 + rb + mf * 16 + ty + 8] = lac[mf * 2 + 1];
        }
    }
    __syncthreads();
#pragma unroll
    for (int mf = 0; mf < 2; mf++) {
        const int r0 = rb + mf * 16 + ty, r1 = r0 + 8;
        const float inv0 = 1.f / (lp[r0] + lp[128 + r0]);
        const float inv1 = 1.f / (lp[r1] + lp[128 + r1]);
        float* o0 = out + ((size_t)(bb * 1024 + q0 + r0)) * 2304 + cc * 768 + hh * 256 + nbO;
        float* o1 = out + ((size_t)(bb * 1024 + q0 + r1)) * 2304 + cc * 768 + hh * 256 + nbO;
#pragma unroll
        for (int nf = 0; nf < 16; nf++) {
            const int ccol = nf * 8 + tx * 2;
            *(float2*)&o0[ccol] = make_float2(Oac[mf][nf][0] * inv0, Oac[mf][nf][1] * inv0);
            *(float2*)&o1[ccol] = make_float2(Oac[mf][nf][2] * inv1, Oac[mf][nf][3] * inv1);
        }
    }
}

// ============================================================
extern "C" void kernel_launch(void* const* d_in, const int* in_sizes, int n_in,
                              void* d_out, int out_size)
{
    const float* x  = (const float*)d_in[0];
    const float* Wq = (const float*)d_in[1];
    const float* bq = (const float*)d_in[2];
    const float* Wk = (const float*)d_in[3];
    const float* bk = (const float*)d_in[4];
    const float* Wv = (const float*)d_in[5];
    const float* bv = (const float*)d_in[6];
    float* out = (float*)d_out;

    cudaFuncSetAttribute(qkv_mma,  cudaFuncAttributeMaxDynamicSharedMemorySize, QKV_SMEM);
    cudaFuncSetAttribute(attn_mma, cudaFuncAttributeMaxDynamicSharedMemorySize, ATT_SMEM);

    qkv_mma<<<dim3(16, 72, 3), 256, QKV_SMEM>>>(x, Wq, bq, Wk, bk, Wv, bv);
    attn_mma<<<dim3(8, 72), 256, ATT_SMEM>>>(out);
}